// round 14
// baseline (speedup 1.0000x reference)
#include <cuda_runtime.h>
#include <cuda_bf16.h>
#include <cuda_fp16.h>
#include <cuda_fp8.h>
#include <math.h>

#define D 128
#define ROWB 256                  // output row stride in BYTES (k: 128 fp16; qv: 128B q + 128B v fp8)
#define MAXN 50000
#define MAXE 600000

// ---------------- scratch (static device globals; no allocation) ----------------
__device__ __nv_bfloat16  g_agg[4][MAXN * D];        // p = layer*2 + edgetype; 0/2: items, 1/3: users
__device__ __nv_bfloat16  g_xbu[MAXN * D];
__device__ __nv_bfloat16  g_xbi[MAXN * D];
__device__ unsigned char  g_qv8[2][MAXN * ROWB];     // fp8 e4m3: q bytes 0..127, v bytes 128..255
__device__ __half         g_k[2][MAXN * D];          // k rows in fp16 (256 B/row)
__device__ __nv_bfloat16  g_Mtb[4][D * D];           // 4 = 2 layers x 2 passes
__device__ __nv_bfloat16  g_Kb[4][D * D];
__device__ __nv_bfloat16  g_Vb[4][D * D];
__device__ float          g_cb[4][D];
__device__ float          g_sum[4];
__device__ int            g_deg[2][MAXN];
__device__ int            g_cur[2][MAXN];
__device__ int            g_bsum[2][260];
__device__ int            g_off_ui[MAXN + 1];
__device__ int            g_off_iu[MAXN + 1];
__device__ int            g_src_ui[MAXE];
__device__ int            g_src_iu[MAXE];

// ------- all-layer weight prep (4 passes) + deg zeroing folded in -------
struct PrepBatch {
    const float* qw[4]; const float* qb[4]; const float* W[4];
    const float* kw[4]; const float* vw[4];
    __nv_bfloat16* Mtb; __nv_bfloat16* Kb; __nv_bfloat16* Vb;
    float* cb; float* psum;
    int* degbase;              // 2*MAXN ints to zero
};

__global__ void prep_batch(PrepBatch pb)
{
    const int p  = blockIdx.y;
    const int bx = blockIdx.x;
    if (bx == 0 && threadIdx.x == 0) pb.psum[p] = 0.f;
    if (bx < 65) {
        int id = bx * 256 + threadIdx.x;
        if (id < D * D) {
            int j = id / D, d = id % D;
            const float* qw = pb.qw[p];
            const float* W  = pb.W[p];
            float s = 0.f;
            #pragma unroll 8
            for (int e = 0; e < D; ++e) s = fmaf(qw[e * D + d], W[e * D + j], s);
            pb.Mtb[p * D * D + j * D + d] = __float2bfloat16(s);
        } else if (id < D * D + D) {
            int j = id - D * D;
            const float* qb = pb.qb[p];
            const float* W  = pb.W[p];
            float s = 0.f;
            #pragma unroll 8
            for (int e = 0; e < D; ++e) s = fmaf(qb[e], W[e * D + j], s);
            pb.cb[p * D + j] = s;
        }
    } else if (bx < 129) {
        int id = (bx - 65) * 256 + threadIdx.x;
        pb.Kb[p * D * D + id] = __float2bfloat16(pb.kw[p][id]);
    } else if (bx < 193) {
        int id = (bx - 129) * 256 + threadIdx.x;
        pb.Vb[p * D * D + id] = __float2bfloat16(pb.vw[p][id]);
    } else {
        // zero deg: 4 y-slices x 98 blocks x 256 threads >= 2*MAXN
        int idx = ((bx - 193) + p * 98) * 256 + threadIdx.x;
        if (idx < 2 * MAXN) pb.degbase[idx] = 0;
    }
}

// ---------------- batched fp32 -> bf16 convert (8 elems/thread, 16B stores) ----------------
struct ConvB { const float* x[2]; __nv_bfloat16* y[2]; int n8[2]; };

__global__ void conv_b16(ConvB cv)
{
    const int t = blockIdx.y;
    int i = blockIdx.x * blockDim.x + threadIdx.x;
    if (i >= cv.n8[t]) return;
    const float4* xp = (const float4*)cv.x[t] + i * 2;
    float4 v0 = xp[0];
    float4 v1 = xp[1];
    __nv_bfloat162 a = __floats2bfloat162_rn(v0.x, v0.y);
    __nv_bfloat162 b = __floats2bfloat162_rn(v0.z, v0.w);
    __nv_bfloat162 c = __floats2bfloat162_rn(v1.x, v1.y);
    __nv_bfloat162 d = __floats2bfloat162_rn(v1.z, v1.w);
    ((uint4*)cv.y[t])[i] = make_uint4(*(unsigned*)&a, *(unsigned*)&b, *(unsigned*)&c, *(unsigned*)&d);
}

// ---------------- bf16 tensor-core batched GEMM ----------------
__device__ __forceinline__ void mma16816(float c[4],
                                         unsigned a0, unsigned a1, unsigned a2, unsigned a3,
                                         unsigned b0, unsigned b1)
{
    asm volatile("mma.sync.aligned.m16n8k16.row.col.f32.bf16.bf16.f32 "
                 "{%0,%1,%2,%3}, {%4,%5,%6,%7}, {%8,%9}, {%0,%1,%2,%3};"
                 : "+f"(c[0]), "+f"(c[1]), "+f"(c[2]), "+f"(c[3])
                 : "r"(a0), "r"(a1), "r"(a2), "r"(a3), "r"(b0), "r"(b1));
}

__device__ __forceinline__ unsigned short enc8(float hi, float lo)
{
    unsigned short u;
    asm("cvt.rn.satfinite.e4m3x2.f32 %0, %1, %2;" : "=h"(u) : "f"(hi), "f"(lo));
    return u;   // low byte = lo, high byte = hi
}

#define GSTRIDE 136   // smem row stride in bf16 elems; 68 words, 68 mod 32 = 4 -> conflict-free

struct GemmBatch {
    const __nv_bfloat16* X[6];
    const __nv_bfloat16* W[6];
    const float*         bias[6];
    char*                C[6];      // byte base; row stride ROWB bytes
    int                  N[6];
    int                  mode[6];   // 0 -> bf16, 1 -> e4m3, 2 -> fp16
};

__global__ __launch_bounds__(256, 3) void gemm_batch(GemmBatch gb)
{
    extern __shared__ __nv_bfloat16 sh[];
    __nv_bfloat16* Xs = sh;                   // [128][GSTRIDE]
    __nv_bfloat16* Ws = sh + 128 * GSTRIDE;   // [128][GSTRIDE]
    const int g = blockIdx.y;
    const int N = gb.N[g];
    const int row0 = blockIdx.x * 128;
    if (row0 >= N) return;
    const __nv_bfloat16* __restrict__ X  = gb.X[g];
    const __nv_bfloat16* __restrict__ Wm = gb.W[g];
    const float* __restrict__ bias       = gb.bias[g];
    char* __restrict__ C                 = gb.C[g];
    const int mode = gb.mode[g];

    const int tid  = threadIdx.x;
    const int warp = tid >> 5, lane = tid & 31;

    #pragma unroll
    for (int i = 0; i < 8; ++i) {
        int seg = tid + i * 256;
        int r = seg >> 4, c = (seg & 15) << 3;
        *(uint4*)(Ws + r * GSTRIDE + c) = *(const uint4*)(Wm + r * D + c);
    }
    #pragma unroll
    for (int i = 0; i < 8; ++i) {
        int seg = tid + i * 256;
        int r = seg >> 4, c = (seg & 15) << 3;
        int gr = row0 + r;
        uint4 val = make_uint4(0u, 0u, 0u, 0u);
        if (gr < N) val = *(const uint4*)(X + (size_t)gr * D + c);
        *(uint4*)(Xs + r * GSTRIDE + c) = val;
    }
    __syncthreads();

    const int wm = warp & 3;
    const int wn = warp >> 2;
    const int qr = lane >> 2;
    const int kq = (lane & 3) * 2;

    float acc[2][8][4];
    #pragma unroll
    for (int m = 0; m < 2; ++m)
        #pragma unroll
        for (int nt = 0; nt < 8; ++nt)
            #pragma unroll
            for (int j = 0; j < 4; ++j) acc[m][nt][j] = 0.f;

    #pragma unroll
    for (int k0 = 0; k0 < D; k0 += 16) {
        unsigned a[2][4];
        #pragma unroll
        for (int m = 0; m < 2; ++m) {
            const __nv_bfloat16* base = Xs + (32 * wm + 16 * m + qr) * GSTRIDE + k0 + kq;
            a[m][0] = *(const unsigned*)(base);
            a[m][1] = *(const unsigned*)(base + 8 * GSTRIDE);
            a[m][2] = *(const unsigned*)(base + 8);
            a[m][3] = *(const unsigned*)(base + 8 * GSTRIDE + 8);
        }
        #pragma unroll
        for (int nt = 0; nt < 8; ++nt) {
            const __nv_bfloat16* bb = Ws + (64 * wn + nt * 8 + qr) * GSTRIDE + k0 + kq;
            unsigned b0 = *(const unsigned*)(bb);
            unsigned b1 = *(const unsigned*)(bb + 8);
            mma16816(acc[0][nt], a[0][0], a[0][1], a[0][2], a[0][3], b0, b1);
            mma16816(acc[1][nt], a[1][0], a[1][1], a[1][2], a[1][3], b0, b1);
        }
    }

    #pragma unroll
    for (int m = 0; m < 2; ++m) {
        int gr0 = row0 + 32 * wm + 16 * m + qr;
        int gr1 = gr0 + 8;
        #pragma unroll
        for (int nt = 0; nt < 8; ++nt) {
            int gc = 64 * wn + nt * 8 + kq;
            float b0f = bias[gc], b1f = bias[gc + 1];
            float v00 = acc[m][nt][0] + b0f, v01 = acc[m][nt][1] + b1f;
            float v10 = acc[m][nt][2] + b0f, v11 = acc[m][nt][3] + b1f;
            if (mode == 1) {
                if (gr0 < N) *(unsigned short*)(C + (size_t)gr0 * ROWB + gc) = enc8(v01, v00);
                if (gr1 < N) *(unsigned short*)(C + (size_t)gr1 * ROWB + gc) = enc8(v11, v10);
            } else if (mode == 2) {
                if (gr0 < N) {
                    __half2 o = __floats2half2_rn(v00, v01);
                    *(__half2*)(C + (size_t)gr0 * ROWB + gc * 2) = o;
                }
                if (gr1 < N) {
                    __half2 o = __floats2half2_rn(v10, v11);
                    *(__half2*)(C + (size_t)gr1 * ROWB + gc * 2) = o;
                }
            } else {
                if (gr0 < N) {
                    __nv_bfloat162 o = __floats2bfloat162_rn(v00, v01);
                    *(__nv_bfloat162*)(C + (size_t)gr0 * ROWB + gc * 2) = o;
                }
                if (gr1 < N) {
                    __nv_bfloat162 o = __floats2bfloat162_rn(v10, v11);
                    *(__nv_bfloat162*)(C + (size_t)gr1 * ROWB + gc * 2) = o;
                }
            }
        }
    }
}

// ---------------- CSR build (batched over both edge types; multi-block scan) ----------------
struct CountB { const int* dst[2]; int* deg[2]; int E[2]; };

__global__ void count_b(CountB cb)
{
    const int t = blockIdx.y;
    const int* __restrict__ dst = cb.dst[t];
    int* __restrict__ deg = cb.deg[t];
    const int E = cb.E[t];
    for (int e = blockIdx.x * blockDim.x + threadIdx.x; e < E; e += gridDim.x * blockDim.x)
        atomicAdd(&deg[dst[e]], 1);
}

struct PartB { const int* deg[2]; int* bsum[2]; int n[2]; };

__global__ __launch_bounds__(256) void partial_b(PartB pp)
{
    const int t = blockIdx.y;
    const int n = pp.n[t];
    const int i = blockIdx.x * 256 + threadIdx.x;
    const int lane = threadIdx.x & 31, wid = threadIdx.x >> 5;
    int v = (i < n) ? pp.deg[t][i] : 0;
    #pragma unroll
    for (int o = 16; o; o >>= 1) v += __shfl_xor_sync(0xffffffffu, v, o);
    __shared__ int ws[8];
    if (lane == 0) ws[wid] = v;
    __syncthreads();
    if (threadIdx.x == 0) {
        int s = 0;
        #pragma unroll
        for (int w = 0; w < 8; ++w) s += ws[w];
        pp.bsum[t][blockIdx.x] = s;
    }
}

struct SSumB { int* bsum[2]; int nblk[2]; };

__global__ __launch_bounds__(512) void scansums_b(SSumB ss)
{
    __shared__ int sh[2][256];
    const int ty = threadIdx.x >> 8;
    const int j  = threadIdx.x & 255;
    const int nb = ss.nblk[ty];
    int v0 = (j < nb) ? ss.bsum[ty][j] : 0;
    sh[ty][j] = v0;
    __syncthreads();
    #pragma unroll
    for (int o = 1; o < 256; o <<= 1) {
        int v = (j >= o) ? sh[ty][j - o] : 0;
        __syncthreads();
        sh[ty][j] += v;
        __syncthreads();
    }
    ss.bsum[ty][j] = sh[ty][j] - v0;      // exclusive prefix
}

struct OffB { const int* deg[2]; const int* bsum[2]; int* off[2]; int* cur[2]; int n[2]; };

__global__ __launch_bounds__(256) void offsets_b(OffB oo)
{
    const int t = blockIdx.y;
    const int n = oo.n[t];
    const int b = blockIdx.x;
    const int i = b * 256 + threadIdx.x;
    const int lane = threadIdx.x & 31, wid = threadIdx.x >> 5;
    int v = (i < n) ? oo.deg[t][i] : 0;
    int incl = v;
    #pragma unroll
    for (int o = 1; o < 32; o <<= 1) {
        int x = __shfl_up_sync(0xffffffffu, incl, o);
        if (lane >= o) incl += x;
    }
    __shared__ int ws[8];
    if (lane == 31) ws[wid] = incl;
    __syncthreads();
    if (wid == 0 && lane < 8) {
        int s = ws[lane];
        int ic = s;
        #pragma unroll
        for (int o = 1; o < 8; o <<= 1) {
            int x = __shfl_up_sync(0xffu, ic, o, 8);
            if (lane >= o) ic += x;
        }
        ws[lane] = ic - s;
    }
    __syncthreads();
    int base = oo.bsum[t][b] + ws[wid] + incl - v;
    if (i < n) { oo.off[t][i] = base; oo.cur[t][i] = base; }
    if (i == n - 1) oo.off[t][n] = base + v;
}

struct FillB { const int* dst[2]; const int* src[2]; int* cur[2]; int* csrc[2]; int E[2]; };

__global__ void fill_b(FillB fb)
{
    const int t = blockIdx.y;
    const int* __restrict__ dst = fb.dst[t];
    const int* __restrict__ src = fb.src[t];
    int* __restrict__ cur = fb.cur[t];
    int* __restrict__ csrc = fb.csrc[t];
    const int E = fb.E[t];
    for (int e = blockIdx.x * blockDim.x + threadIdx.x; e < E; e += gridDim.x * blockDim.x) {
        int p = atomicAdd(&cur[dst[e]], 1);
        csrc[p] = src[e];
    }
}

// ------------- fused edge pass: 8-lane-group-per-edge, half2 math, fp16 k ----------------
struct EdgeBatch {
    const unsigned char* qv[2];
    const __half* k[2];
    const int* off[2];
    const int* csrc[2];
    __nv_bfloat16* agg[2];
    float* psum;                 // [2]
    int n[2];
};

// decode uint (4 fp8) -> two half2
__device__ __forceinline__ void dec8h(unsigned u, __half2& a, __half2& b)
{
    unsigned r0, r1;
    asm("cvt.rn.f16x2.e4m3x2 %0, %1;" : "=r"(r0) : "h"((unsigned short)(u & 0xffffu)));
    asm("cvt.rn.f16x2.e4m3x2 %0, %1;" : "=r"(r1) : "h"((unsigned short)(u >> 16)));
    a = *(__half2*)&r0;
    b = *(__half2*)&r1;
}

__device__ __forceinline__ float lrexp(float p)
{
    float sc = p * 0.08838834764831845f;     // 1/sqrt(128)
    sc = sc > 0.f ? sc : 0.01f * sc;         // leaky_relu
    return __expf(sc);
}

__device__ __forceinline__ float dot16h(uint4 qw, const __half2* k2)
{
    __half2 a0, a1, b0, b1, c0, c1, d0, d1;
    dec8h(qw.x, a0, a1);
    dec8h(qw.y, b0, b1);
    dec8h(qw.z, c0, c1);
    dec8h(qw.w, d0, d1);
    __half2 s = __hmul2(a0, k2[0]);
    s = __hfma2(a1, k2[1], s);
    s = __hfma2(b0, k2[2], s);
    s = __hfma2(b1, k2[3], s);
    s = __hfma2(c0, k2[4], s);
    s = __hfma2(c1, k2[5], s);
    s = __hfma2(d0, k2[6], s);
    s = __hfma2(d1, k2[7], s);
    float2 f = __half22float2(s);
    return f.x + f.y;
}

__device__ __forceinline__ void acc16h(__half2 e2, uint4 vw, __half2* acc2)
{
    __half2 a0, a1, b0, b1, c0, c1, d0, d1;
    dec8h(vw.x, a0, a1);
    dec8h(vw.y, b0, b1);
    dec8h(vw.z, c0, c1);
    dec8h(vw.w, d0, d1);
    acc2[0] = __hfma2(e2, a0, acc2[0]);
    acc2[1] = __hfma2(e2, a1, acc2[1]);
    acc2[2] = __hfma2(e2, b0, acc2[2]);
    acc2[3] = __hfma2(e2, b1, acc2[3]);
    acc2[4] = __hfma2(e2, c0, acc2[4]);
    acc2[5] = __hfma2(e2, c1, acc2[5]);
    acc2[6] = __hfma2(e2, d0, acc2[6]);
    acc2[7] = __hfma2(e2, d1, acc2[7]);
}

__global__ __launch_bounds__(256) void fused_edge_batch(EdgeBatch eb)
{
    const int p    = blockIdx.y;
    const int lane = threadIdx.x & 31;
    const int grp  = lane >> 3;          // 0..3: which edge within a 4-edge slab
    const int gl   = lane & 7;           // 0..7: which 16-byte slice of the row
    const int warp = (blockIdx.x * 256 + threadIdx.x) >> 5;
    const int nw   = (gridDim.x * 256) >> 5;
    const unsigned char* __restrict__ qv = eb.qv[p] + gl * 16;
    const __half* __restrict__ kk = eb.k[p];
    const int* __restrict__ off  = eb.off[p];
    const int* __restrict__ csrc = eb.csrc[p];
    __nv_bfloat16* __restrict__ agg = eb.agg[p];
    const int n = eb.n[p];

    float S = 0.f;
    for (int node = warp; node < n; node += nw) {
        // k slice: dims gl*16 .. +15, loaded directly as 8 half2
        __half2 k2[8];
        {
            const __half* krow = kk + (size_t)node * D + gl * 16;
            uint4 kk0 = *(const uint4*)(krow);
            uint4 kk1 = *(const uint4*)(krow + 8);
            k2[0] = *(__half2*)&kk0.x; k2[1] = *(__half2*)&kk0.y;
            k2[2] = *(__half2*)&kk0.z; k2[3] = *(__half2*)&kk0.w;
            k2[4] = *(__half2*)&kk1.x; k2[5] = *(__half2*)&kk1.y;
            k2[6] = *(__half2*)&kk1.z; k2[7] = *(__half2*)&kk1.w;
        }
        __half2 acc2[8];
        #pragma unroll
        for (int i = 0; i < 8; ++i) acc2[i] = __floats2half2_rn(0.f, 0.f);

        const int beg = off[node], end = off[node + 1];
        int base = beg;
        // 2x-unrolled: 8 edges per warp iteration (two per group)
        for (; base + 8 <= end; base += 8) {
            int cA = csrc[base + grp];
            int cB = csrc[base + 4 + grp];
            const unsigned char* bpA = qv + (size_t)cA * ROWB;
            const unsigned char* bpB = qv + (size_t)cB * ROWB;
            uint4 qA = *(const uint4*)(bpA);
            uint4 qB = *(const uint4*)(bpB);
            uint4 vA = *(const uint4*)(bpA + 128);
            uint4 vB = *(const uint4*)(bpB + 128);
            float pA = dot16h(qA, k2);
            float pB = dot16h(qB, k2);
            #pragma unroll
            for (int o = 4; o; o >>= 1) {
                pA += __shfl_xor_sync(0xffffffffu, pA, o);
                pB += __shfl_xor_sync(0xffffffffu, pB, o);
            }
            float eA = lrexp(pA);
            float eB = lrexp(pB);
            acc16h(__float2half2_rn(eA), vA, acc2);
            acc16h(__float2half2_rn(eB), vB, acc2);
            if (gl == 0) S += eA + eB;
        }
        for (; base < end; base += 4) {
            int idx = base + grp;
            bool valid = idx < end;
            int c = valid ? csrc[idx] : 0;
            const unsigned char* bp = qv + (size_t)c * ROWB;
            uint4 q = *(const uint4*)(bp);
            uint4 v = *(const uint4*)(bp + 128);
            float pe = dot16h(q, k2);
            #pragma unroll
            for (int o = 4; o; o >>= 1) pe += __shfl_xor_sync(0xffffffffu, pe, o);
            float e = valid ? lrexp(pe) : 0.f;
            acc16h(__float2half2_rn(e), v, acc2);
            if (gl == 0) S += e;
        }

        // cross-group combine: lanes with same gl across the 4 groups hold partial sums
        #pragma unroll
        for (int i = 0; i < 8; ++i) {
            unsigned u = *(unsigned*)&acc2[i];
            unsigned u8  = __shfl_xor_sync(0xffffffffu, u, 8);
            __half2 t = __hadd2(acc2[i], *(__half2*)&u8);
            unsigned ut = *(unsigned*)&t;
            unsigned u16 = __shfl_xor_sync(0xffffffffu, ut, 16);
            acc2[i] = __hadd2(t, *(__half2*)&u16);
        }
        if (grp == 0) {
            unsigned w[8];
            #pragma unroll
            for (int j = 0; j < 8; ++j) {
                float2 f = __half22float2(acc2[j]);
                __nv_bfloat162 b2 = __floats2bfloat162_rn(f.x, f.y);
                w[j] = *(unsigned*)&b2;
            }
            __nv_bfloat16* arow = agg + (size_t)node * D + gl * 16;
            *(uint4*)(arow)     = make_uint4(w[0], w[1], w[2], w[3]);
            *(uint4*)(arow + 8) = make_uint4(w[4], w[5], w[6], w[7]);
        }
    }
    // S nonzero only on gl==0 lanes; warp-reduce then one atomic
    #pragma unroll
    for (int o = 16; o; o >>= 1) S += __shfl_xor_sync(0xffffffffu, S, o);
    if (lane == 0 && S != 0.f) atomicAdd(&eb.psum[p], S);
}

// ---- layer-0 epilogue: xb = bf16(x + agg/S)  (8 elems/thread, bf16-only output) ----
struct Axpy0 {
    const float* xin[2];
    const __nv_bfloat16* agg[2];
    const float* gsum[2];
    __nv_bfloat16* outb[2];
    int n8[2];
};

__global__ void axpy0_batch(Axpy0 ab)
{
    const int t = blockIdx.y;
    int i = blockIdx.x * blockDim.x + threadIdx.x;
    if (i >= ab.n8[t]) return;
    float inv = 1.0f / *ab.gsum[t];
    const float4* xp = (const float4*)ab.xin[t] + i * 2;
    float4 x0 = xp[0];
    float4 x1 = xp[1];
    uint4 ag = ((const uint4*)ab.agg[t])[i];
    float2 a0 = __bfloat1622float2(*(__nv_bfloat162*)&ag.x);
    float2 a1 = __bfloat1622float2(*(__nv_bfloat162*)&ag.y);
    float2 a2 = __bfloat1622float2(*(__nv_bfloat162*)&ag.z);
    float2 a3 = __bfloat1622float2(*(__nv_bfloat162*)&ag.w);
    __nv_bfloat162 o0 = __floats2bfloat162_rn(fmaf(inv, a0.x, x0.x), fmaf(inv, a0.y, x0.y));
    __nv_bfloat162 o1 = __floats2bfloat162_rn(fmaf(inv, a1.x, x0.z), fmaf(inv, a1.y, x0.w));
    __nv_bfloat162 o2 = __floats2bfloat162_rn(fmaf(inv, a2.x, x1.x), fmaf(inv, a2.y, x1.y));
    __nv_bfloat162 o3 = __floats2bfloat162_rn(fmaf(inv, a3.x, x1.z), fmaf(inv, a3.y, x1.w));
    ((uint4*)ab.outb[t])[i] = make_uint4(*(unsigned*)&o0, *(unsigned*)&o1,
                                         *(unsigned*)&o2, *(unsigned*)&o3);
}

// ---- layer-1 epilogue: out = x + aggA/SA + aggB/SB  (fp32 output) ----
struct Axpy1 {
    const float* xin[2];
    const __nv_bfloat16* aggA[2];   // layer-0 agg
    const __nv_bfloat16* aggB[2];   // layer-1 agg
    const float* gsumA[2];
    const float* gsumB[2];
    float* out[2];
    int n8[2];
};

__global__ void axpy1_batch(Axpy1 ab)
{
    const int t = blockIdx.y;
    int i = blockIdx.x * blockDim.x + threadIdx.x;
    if (i >= ab.n8[t]) return;
    float invA = 1.0f / *ab.gsumA[t];
    float invB = 1.0f / *ab.gsumB[t];
    const float4* xp = (const float4*)ab.xin[t] + i * 2;
    float4 x0 = xp[0];
    float4 x1 = xp[1];
    uint4 gA = ((const uint4*)ab.aggA[t])[i];
    uint4 gB = ((const uint4*)ab.aggB[t])[i];
    float2 A0 = __bfloat1622float2(*(__nv_bfloat162*)&gA.x);
    float2 A1 = __bfloat1622float2(*(__nv_bfloat162*)&gA.y);
    float2 A2 = __bfloat1622float2(*(__nv_bfloat162*)&gA.z);
    float2 A3 = __bfloat1622float2(*(__nv_bfloat162*)&gA.w);
    float2 B0 = __bfloat1622float2(*(__nv_bfloat162*)&gB.x);
    float2 B1 = __bfloat1622float2(*(__nv_bfloat162*)&gB.y);
    float2 B2 = __bfloat1622float2(*(__nv_bfloat162*)&gB.z);
    float2 B3 = __bfloat1622float2(*(__nv_bfloat162*)&gB.w);
    float4 o0, o1;
    o0.x = fmaf(invB, B0.x, fmaf(invA, A0.x, x0.x));
    o0.y = fmaf(invB, B0.y, fmaf(invA, A0.y, x0.y));
    o0.z = fmaf(invB, B1.x, fmaf(invA, A1.x, x0.z));
    o0.w = fmaf(invB, B1.y, fmaf(invA, A1.y, x0.w));
    o1.x = fmaf(invB, B2.x, fmaf(invA, A2.x, x1.x));
    o1.y = fmaf(invB, B2.y, fmaf(invA, A2.y, x1.y));
    o1.z = fmaf(invB, B3.x, fmaf(invA, A3.x, x1.z));
    o1.w = fmaf(invB, B3.y, fmaf(invA, A3.y, x1.w));
    float4* op = (float4*)ab.out[t] + i * 2;
    op[0] = o0;
    op[1] = o1;
}

// ---------------- host-side orchestration ----------------
#define GEMM_SMEM (2 * 128 * GSTRIDE * (int)sizeof(__nv_bfloat16))

extern "C" void kernel_launch(void* const* d_in, const int* in_sizes, int n_in,
                              void* d_out, int out_size)
{
    const float* x_user = (const float*)d_in[0];
    const float* x_item = (const float*)d_in[1];
    const int*   ei_ui  = (const int*)d_in[2];
    const int*   ei_iu  = (const int*)d_in[3];
    const float* q_w_user = (const float*)d_in[4];
    const float* q_b_user = (const float*)d_in[5];
    const float* k_w_user = (const float*)d_in[6];
    const float* k_b_user = (const float*)d_in[7];
    const float* v_w_user = (const float*)d_in[8];
    const float* v_b_user = (const float*)d_in[9];
    const float* q_w_item = (const float*)d_in[10];
    const float* q_b_item = (const float*)d_in[11];
    const float* k_w_item = (const float*)d_in[12];
    const float* k_b_item = (const float*)d_in[13];
    const float* v_w_item = (const float*)d_in[14];
    const float* v_b_item = (const float*)d_in[15];
    const float* W_ui = (const float*)d_in[16];
    const float* W_iu = (const float*)d_in[17];

    const int NU = in_sizes[0] / D;
    const int NI = in_sizes[1] / D;
    const int E_ui = in_sizes[2] / 2;
    const int E_iu = in_sizes[3] / 2;

    cudaFuncSetAttribute(gemm_batch, cudaFuncAttributeMaxDynamicSharedMemorySize, GEMM_SMEM);

    float *cb, *psum;
    __nv_bfloat16 *agg, *xbu, *xbi, *Mtb, *Kb, *Vb;
    __half *kb0, *kb1;
    unsigned char *qv0, *qv1;
    int *deg0, *deg1, *cur0, *cur1, *bs0, *bs1, *off_ui, *off_iu, *src_ui_c, *src_iu_c;
    cudaGetSymbolAddress((void**)&agg, g_agg);       // [4][MAXN*D]
    cudaGetSymbolAddress((void**)&xbu, g_xbu);
    cudaGetSymbolAddress((void**)&xbi, g_xbi);
    cudaGetSymbolAddress((void**)&qv0, g_qv8);
    qv1 = qv0 + (size_t)MAXN * ROWB;
    cudaGetSymbolAddress((void**)&kb0, g_k);
    kb1 = kb0 + (size_t)MAXN * D;
    cudaGetSymbolAddress((void**)&Mtb, g_Mtb);
    cudaGetSymbolAddress((void**)&Kb, g_Kb);
    cudaGetSymbolAddress((void**)&Vb, g_Vb);
    cudaGetSymbolAddress((void**)&cb, g_cb);
    cudaGetSymbolAddress((void**)&psum, g_sum);
    cudaGetSymbolAddress((void**)&deg0, g_deg);
    deg1 = deg0 + MAXN;
    cudaGetSymbolAddress((void**)&cur0, g_cur);
    cur1 = cur0 + MAXN;
    cudaGetSymbolAddress((void**)&bs0, g_bsum);
    bs1 = bs0 + 260;
    cudaGetSymbolAddress((void**)&off_ui, g_off_ui);
    cudaGetSymbolAddress((void**)&off_iu, g_off_iu);
    cudaGetSymbolAddress((void**)&src_ui_c, g_src_ui);
    cudaGetSymbolAddress((void**)&src_iu_c, g_src_iu);

    __nv_bfloat16* aggP[4];
    for (int p = 0; p < 4; ++p) aggP[p] = agg + (size_t)p * MAXN * D;

    const int* src_ui = ei_ui;
    const int* dst_ui = ei_ui + E_ui;
    const int* src_iu = ei_iu;
    const int* dst_iu = ei_iu + E_iu;

    // --- weight prep + deg zeroing (one launch, must precede count_b) ---
    {
        PrepBatch pb;
        for (int l = 0; l < 2; ++l) {
            const size_t wo = (size_t)l * D * D;
            const size_t bo = (size_t)l * D;
            pb.qw[2*l+0] = q_w_user + wo; pb.qb[2*l+0] = q_b_user + bo; pb.W[2*l+0] = W_ui + wo;
            pb.kw[2*l+0] = k_w_item + wo; pb.vw[2*l+0] = v_w_user + wo;
            pb.qw[2*l+1] = q_w_item + wo; pb.qb[2*l+1] = q_b_item + bo; pb.W[2*l+1] = W_iu + wo;
            pb.kw[2*l+1] = k_w_user + wo; pb.vw[2*l+1] = v_w_item + wo;
        }
        pb.Mtb = Mtb; pb.Kb = Kb; pb.Vb = Vb; pb.cb = cb; pb.psum = psum;
        pb.degbase = deg0;
        prep_batch<<<dim3(291, 4), 256>>>(pb);
    }

    // --- CSR by dst for both edge types (multi-block scan; built once, reused by both layers) ---
    CountB cbt;
    cbt.dst[0] = dst_ui; cbt.deg[0] = deg0; cbt.E[0] = E_ui;
    cbt.dst[1] = dst_iu; cbt.deg[1] = deg1; cbt.E[1] = E_iu;
    count_b<<<dim3(512, 2), 256>>>(cbt);

    const int nblk0 = (NI + 255) / 256;
    const int nblk1 = (NU + 255) / 256;
    const int nblkM = (nblk0 > nblk1) ? nblk0 : nblk1;

    PartB pp;
    pp.deg[0] = deg0; pp.bsum[0] = bs0; pp.n[0] = NI;
    pp.deg[1] = deg1; pp.bsum[1] = bs1; pp.n[1] = NU;
    partial_b<<<dim3(nblkM, 2), 256>>>(pp);

    SSumB ss;
    ss.bsum[0] = bs0; ss.nblk[0] = nblk0;
    ss.bsum[1] = bs1; ss.nblk[1] = nblk1;
    scansums_b<<<1, 512>>>(ss);

    OffB oo;
    oo.deg[0] = deg0; oo.bsum[0] = bs0; oo.off[0] = off_ui; oo.cur[0] = cur0; oo.n[0] = NI;
    oo.deg[1] = deg1; oo.bsum[1] = bs1; oo.off[1] = off_iu; oo.cur[1] = cur1; oo.n[1] = NU;
    offsets_b<<<dim3(nblkM, 2), 256>>>(oo);

    FillB fbt;
    fbt.dst[0] = dst_ui; fbt.src[0] = src_ui; fbt.cur[0] = cur0; fbt.csrc[0] = src_ui_c; fbt.E[0] = E_ui;
    fbt.dst[1] = dst_iu; fbt.src[1] = src_iu; fbt.cur[1] = cur1; fbt.csrc[1] = src_iu_c; fbt.E[1] = E_iu;
    fill_b<<<dim3(512, 2), 256>>>(fbt);

    // --- bf16 copies of layer-0 inputs (8 elems/thread) ---
    const int maxN = (NU > NI) ? NU : NI;
    const int n8grid = (maxN * D / 8 + 255) / 256;
    ConvB cv;
    cv.x[0] = x_user; cv.y[0] = xbu; cv.n8[0] = NU * D / 8;
    cv.x[1] = x_item; cv.y[1] = xbi; cv.n8[1] = NI * D / 8;
    conv_b16<<<dim3(n8grid, 2), 256>>>(cv);

    float* out_f = (float*)d_out;

    for (int l = 0; l < 2; ++l) {
        const size_t bo = (size_t)l * D;
        const int p0 = 2 * l, p1 = 2 * l + 1;

        GemmBatch gb;
        // pass 0: user->item (q/v from user -> fp8 qv0; k from item -> fp16 kb0)
        gb.X[0] = xbu; gb.W[0] = Mtb + p0 * D * D; gb.bias[0] = cb + p0 * D;    gb.C[0] = (char*)qv0;         gb.N[0] = NU; gb.mode[0] = 1;
        gb.X[1] = xbi; gb.W[1] = Kb + p0 * D * D;  gb.bias[1] = k_b_item + bo; gb.C[1] = (char*)kb0;         gb.N[1] = NI; gb.mode[1] = 2;
        gb.X[2] = xbu; gb.W[2] = Vb + p0 * D * D;  gb.bias[2] = v_b_user + bo; gb.C[2] = (char*)(qv0 + 128); gb.N[2] = NU; gb.mode[2] = 1;
        // pass 1: item->user
        gb.X[3] = xbi; gb.W[3] = Mtb + p1 * D * D; gb.bias[3] = cb + p1 * D;    gb.C[3] = (char*)qv1;         gb.N[3] = NI; gb.mode[3] = 1;
        gb.X[4] = xbu; gb.W[4] = Kb + p1 * D * D;  gb.bias[4] = k_b_user + bo; gb.C[4] = (char*)kb1;         gb.N[4] = NU; gb.mode[4] = 2;
        gb.X[5] = xbi; gb.W[5] = Vb + p1 * D * D;  gb.bias[5] = v_b_item + bo; gb.C[5] = (char*)(qv1 + 128); gb.N[5] = NI; gb.mode[5] = 1;
        gemm_batch<<<dim3((maxN + 127) / 128, 6), 256, GEMM_SMEM>>>(gb);

        EdgeBatch eb;
        eb.qv[0] = qv0; eb.k[0] = kb0;
        eb.off[0] = off_ui; eb.csrc[0] = src_ui_c; eb.agg[0] = aggP[p0]; eb.n[0] = NI;
        eb.qv[1] = qv1; eb.k[1] = kb1;
        eb.off[1] = off_iu; eb.csrc[1] = src_iu_c; eb.agg[1] = aggP[p1]; eb.n[1] = NU;
        eb.psum = psum + 2 * l;
        fused_edge_batch<<<dim3(1024, 2), 256>>>(eb);

        if (l == 0) {
            // layer-0 epilogue: only bf16 features for layer 1
            Axpy0 a0;
            a0.xin[0] = x_user; a0.agg[0] = aggP[1]; a0.gsum[0] = psum + 1; a0.outb[0] = xbu; a0.n8[0] = NU * D / 8;
            a0.xin[1] = x_item; a0.agg[1] = aggP[0]; a0.gsum[1] = psum + 0; a0.outb[1] = xbi; a0.n8[1] = NI * D / 8;
            axpy0_batch<<<dim3(n8grid, 2), 256>>>(a0);
        } else {
            // final output: out = x + agg_l0/S_l0 + agg_l1/S_l1 (fp32)
            Axpy1 a1;
            a1.xin[0] = x_user; a1.aggA[0] = aggP[1]; a1.aggB[0] = aggP[3];
            a1.gsumA[0] = psum + 1; a1.gsumB[0] = psum + 3;
            a1.out[0] = out_f; a1.n8[0] = NU * D / 8;
            a1.xin[1] = x_item; a1.aggA[1] = aggP[0]; a1.aggB[1] = aggP[2];
            a1.gsumA[1] = psum + 0; a1.gsumB[1] = psum + 2;
            a1.out[1] = out_f + (size_t)NU * D; a1.n8[1] = NI * D / 8;
            axpy1_batch<<<dim3(n8grid, 2), 256>>>(a1);
        }
    }
}

// round 15
// speedup vs baseline: 1.0347x; 1.0347x over previous
#include <cuda_runtime.h>
#include <cuda_bf16.h>
#include <cuda_fp16.h>
#include <cuda_fp8.h>
#include <math.h>

#define D 128
#define ROWB 256                  // output row stride in BYTES (k: 128 fp16; qv: 128B q + 128B v fp8)
#define MAXN 50000
#define MAXE 600000

// ---------------- scratch (static device globals; no allocation) ----------------
__device__ __nv_bfloat16  g_agg[4][MAXN * D];        // p = layer*2 + edgetype; 0/2: items, 1/3: users
__device__ __nv_bfloat16  g_xbu[MAXN * D];
__device__ __nv_bfloat16  g_xbi[MAXN * D];
__device__ unsigned char  g_qv8[2][MAXN * ROWB];     // fp8 e4m3: q bytes 0..127, v bytes 128..255
__device__ __half         g_k[2][MAXN * D];          // k rows in fp16 (256 B/row)
__device__ __nv_bfloat16  g_Mtb[4][D * D];           // 4 = 2 layers x 2 passes
__device__ __nv_bfloat16  g_Kb[4][D * D];
__device__ __nv_bfloat16  g_Vb[4][D * D];
__device__ float          g_cb[4][D];
__device__ float          g_sum[4];
__device__ int            g_deg[2][MAXN];
__device__ int            g_cur[2][MAXN];
__device__ int            g_bsum[2][260];
__device__ int            g_off_ui[MAXN + 1];
__device__ int            g_off_iu[MAXN + 1];
__device__ int            g_src_ui[MAXE];
__device__ int            g_src_iu[MAXE];

// ------- all-layer weight prep (4 passes: layer*2 + edgetype) -------
struct PrepBatch {
    const float* qw[4]; const float* qb[4]; const float* W[4];
    const float* kw[4]; const float* vw[4];
    __nv_bfloat16* Mtb; __nv_bfloat16* Kb; __nv_bfloat16* Vb;
    float* cb; float* psum;
};

__global__ void prep_batch(PrepBatch pb)
{
    const int p  = blockIdx.y;
    const int bx = blockIdx.x;
    if (bx == 0 && threadIdx.x == 0) pb.psum[p] = 0.f;
    if (bx < 65) {
        int id = bx * 256 + threadIdx.x;
        if (id < D * D) {
            int j = id / D, d = id % D;
            const float* qw = pb.qw[p];
            const float* W  = pb.W[p];
            float s = 0.f;
            #pragma unroll 8
            for (int e = 0; e < D; ++e) s = fmaf(qw[e * D + d], W[e * D + j], s);
            pb.Mtb[p * D * D + j * D + d] = __float2bfloat16(s);
        } else if (id < D * D + D) {
            int j = id - D * D;
            const float* qb = pb.qb[p];
            const float* W  = pb.W[p];
            float s = 0.f;
            #pragma unroll 8
            for (int e = 0; e < D; ++e) s = fmaf(qb[e], W[e * D + j], s);
            pb.cb[p * D + j] = s;
        }
    } else if (bx < 129) {
        int id = (bx - 65) * 256 + threadIdx.x;
        pb.Kb[p * D * D + id] = __float2bfloat16(pb.kw[p][id]);
    } else {
        int id = (bx - 129) * 256 + threadIdx.x;
        pb.Vb[p * D * D + id] = __float2bfloat16(pb.vw[p][id]);
    }
}

// ---------------- batched fp32 -> bf16 convert (8 elems/thread, 16B stores) ----------------
struct ConvB { const float* x[2]; __nv_bfloat16* y[2]; int n8[2]; };

__global__ void conv_b16(ConvB cv)
{
    const int t = blockIdx.y;
    int i = blockIdx.x * blockDim.x + threadIdx.x;
    if (i >= cv.n8[t]) return;
    const float4* xp = (const float4*)cv.x[t] + i * 2;
    float4 v0 = xp[0];
    float4 v1 = xp[1];
    __nv_bfloat162 a = __floats2bfloat162_rn(v0.x, v0.y);
    __nv_bfloat162 b = __floats2bfloat162_rn(v0.z, v0.w);
    __nv_bfloat162 c = __floats2bfloat162_rn(v1.x, v1.y);
    __nv_bfloat162 d = __floats2bfloat162_rn(v1.z, v1.w);
    ((uint4*)cv.y[t])[i] = make_uint4(*(unsigned*)&a, *(unsigned*)&b, *(unsigned*)&c, *(unsigned*)&d);
}

// ---------------- bf16 tensor-core batched GEMM ----------------
__device__ __forceinline__ void mma16816(float c[4],
                                         unsigned a0, unsigned a1, unsigned a2, unsigned a3,
                                         unsigned b0, unsigned b1)
{
    asm volatile("mma.sync.aligned.m16n8k16.row.col.f32.bf16.bf16.f32 "
                 "{%0,%1,%2,%3}, {%4,%5,%6,%7}, {%8,%9}, {%0,%1,%2,%3};"
                 : "+f"(c[0]), "+f"(c[1]), "+f"(c[2]), "+f"(c[3])
                 : "r"(a0), "r"(a1), "r"(a2), "r"(a3), "r"(b0), "r"(b1));
}

__device__ __forceinline__ unsigned short enc8(float hi, float lo)
{
    unsigned short u;
    asm("cvt.rn.satfinite.e4m3x2.f32 %0, %1, %2;" : "=h"(u) : "f"(hi), "f"(lo));
    return u;   // low byte = lo, high byte = hi
}

#define GSTRIDE 136   // smem row stride in bf16 elems; 68 words, 68 mod 32 = 4 -> conflict-free

struct GemmBatch {
    const __nv_bfloat16* X[6];
    const __nv_bfloat16* W[6];
    const float*         bias[6];
    char*                C[6];      // byte base; row stride ROWB bytes
    int                  N[6];
    int                  mode[6];   // 0 -> bf16, 1 -> e4m3, 2 -> fp16
};

__global__ __launch_bounds__(256, 3) void gemm_batch(GemmBatch gb)
{
    extern __shared__ __nv_bfloat16 sh[];
    __nv_bfloat16* Xs = sh;                   // [128][GSTRIDE]
    __nv_bfloat16* Ws = sh + 128 * GSTRIDE;   // [128][GSTRIDE]
    const int g = blockIdx.y;
    const int N = gb.N[g];
    const int row0 = blockIdx.x * 128;
    if (row0 >= N) return;
    const __nv_bfloat16* __restrict__ X  = gb.X[g];
    const __nv_bfloat16* __restrict__ Wm = gb.W[g];
    const float* __restrict__ bias       = gb.bias[g];
    char* __restrict__ C                 = gb.C[g];
    const int mode = gb.mode[g];

    const int tid  = threadIdx.x;
    const int warp = tid >> 5, lane = tid & 31;

    #pragma unroll
    for (int i = 0; i < 8; ++i) {
        int seg = tid + i * 256;
        int r = seg >> 4, c = (seg & 15) << 3;
        *(uint4*)(Ws + r * GSTRIDE + c) = *(const uint4*)(Wm + r * D + c);
    }
    #pragma unroll
    for (int i = 0; i < 8; ++i) {
        int seg = tid + i * 256;
        int r = seg >> 4, c = (seg & 15) << 3;
        int gr = row0 + r;
        uint4 val = make_uint4(0u, 0u, 0u, 0u);
        if (gr < N) val = *(const uint4*)(X + (size_t)gr * D + c);
        *(uint4*)(Xs + r * GSTRIDE + c) = val;
    }
    __syncthreads();

    const int wm = warp & 3;
    const int wn = warp >> 2;
    const int qr = lane >> 2;
    const int kq = (lane & 3) * 2;

    float acc[2][8][4];
    #pragma unroll
    for (int m = 0; m < 2; ++m)
        #pragma unroll
        for (int nt = 0; nt < 8; ++nt)
            #pragma unroll
            for (int j = 0; j < 4; ++j) acc[m][nt][j] = 0.f;

    #pragma unroll
    for (int k0 = 0; k0 < D; k0 += 16) {
        unsigned a[2][4];
        #pragma unroll
        for (int m = 0; m < 2; ++m) {
            const __nv_bfloat16* base = Xs + (32 * wm + 16 * m + qr) * GSTRIDE + k0 + kq;
            a[m][0] = *(const unsigned*)(base);
            a[m][1] = *(const unsigned*)(base + 8 * GSTRIDE);
            a[m][2] = *(const unsigned*)(base + 8);
            a[m][3] = *(const unsigned*)(base + 8 * GSTRIDE + 8);
        }
        #pragma unroll
        for (int nt = 0; nt < 8; ++nt) {
            const __nv_bfloat16* bb = Ws + (64 * wn + nt * 8 + qr) * GSTRIDE + k0 + kq;
            unsigned b0 = *(const unsigned*)(bb);
            unsigned b1 = *(const unsigned*)(bb + 8);
            mma16816(acc[0][nt], a[0][0], a[0][1], a[0][2], a[0][3], b0, b1);
            mma16816(acc[1][nt], a[1][0], a[1][1], a[1][2], a[1][3], b0, b1);
        }
    }

    #pragma unroll
    for (int m = 0; m < 2; ++m) {
        int gr0 = row0 + 32 * wm + 16 * m + qr;
        int gr1 = gr0 + 8;
        #pragma unroll
        for (int nt = 0; nt < 8; ++nt) {
            int gc = 64 * wn + nt * 8 + kq;
            float b0f = bias[gc], b1f = bias[gc + 1];
            float v00 = acc[m][nt][0] + b0f, v01 = acc[m][nt][1] + b1f;
            float v10 = acc[m][nt][2] + b0f, v11 = acc[m][nt][3] + b1f;
            if (mode == 1) {
                if (gr0 < N) *(unsigned short*)(C + (size_t)gr0 * ROWB + gc) = enc8(v01, v00);
                if (gr1 < N) *(unsigned short*)(C + (size_t)gr1 * ROWB + gc) = enc8(v11, v10);
            } else if (mode == 2) {
                if (gr0 < N) {
                    __half2 o = __floats2half2_rn(v00, v01);
                    *(__half2*)(C + (size_t)gr0 * ROWB + gc * 2) = o;
                }
                if (gr1 < N) {
                    __half2 o = __floats2half2_rn(v10, v11);
                    *(__half2*)(C + (size_t)gr1 * ROWB + gc * 2) = o;
                }
            } else {
                if (gr0 < N) {
                    __nv_bfloat162 o = __floats2bfloat162_rn(v00, v01);
                    *(__nv_bfloat162*)(C + (size_t)gr0 * ROWB + gc * 2) = o;
                }
                if (gr1 < N) {
                    __nv_bfloat162 o = __floats2bfloat162_rn(v10, v11);
                    *(__nv_bfloat162*)(C + (size_t)gr1 * ROWB + gc * 2) = o;
                }
            }
        }
    }
}

// ---------------- CSR build (batched over both edge types; multi-block scan) ----------------
struct CountB { const int* dst[2]; int* deg[2]; int E[2]; };

__global__ void count_b(CountB cb)
{
    const int t = blockIdx.y;
    const int* __restrict__ dst = cb.dst[t];
    int* __restrict__ deg = cb.deg[t];
    const int E = cb.E[t];
    for (int e = blockIdx.x * blockDim.x + threadIdx.x; e < E; e += gridDim.x * blockDim.x)
        atomicAdd(&deg[dst[e]], 1);
}

struct PartB { const int* deg[2]; int* bsum[2]; int n[2]; };

__global__ __launch_bounds__(256) void partial_b(PartB pp)
{
    const int t = blockIdx.y;
    const int n = pp.n[t];
    const int i = blockIdx.x * 256 + threadIdx.x;
    const int lane = threadIdx.x & 31, wid = threadIdx.x >> 5;
    int v = (i < n) ? pp.deg[t][i] : 0;
    #pragma unroll
    for (int o = 16; o; o >>= 1) v += __shfl_xor_sync(0xffffffffu, v, o);
    __shared__ int ws[8];
    if (lane == 0) ws[wid] = v;
    __syncthreads();
    if (threadIdx.x == 0) {
        int s = 0;
        #pragma unroll
        for (int w = 0; w < 8; ++w) s += ws[w];
        pp.bsum[t][blockIdx.x] = s;
    }
}

struct SSumB { int* bsum[2]; int nblk[2]; };

__global__ __launch_bounds__(512) void scansums_b(SSumB ss)
{
    __shared__ int sh[2][256];
    const int ty = threadIdx.x >> 8;
    const int j  = threadIdx.x & 255;
    const int nb = ss.nblk[ty];
    int v0 = (j < nb) ? ss.bsum[ty][j] : 0;
    sh[ty][j] = v0;
    __syncthreads();
    #pragma unroll
    for (int o = 1; o < 256; o <<= 1) {
        int v = (j >= o) ? sh[ty][j - o] : 0;
        __syncthreads();
        sh[ty][j] += v;
        __syncthreads();
    }
    ss.bsum[ty][j] = sh[ty][j] - v0;      // exclusive prefix
}

struct OffB { const int* deg[2]; const int* bsum[2]; int* off[2]; int* cur[2]; int n[2]; };

__global__ __launch_bounds__(256) void offsets_b(OffB oo)
{
    const int t = blockIdx.y;
    const int n = oo.n[t];
    const int b = blockIdx.x;
    const int i = b * 256 + threadIdx.x;
    const int lane = threadIdx.x & 31, wid = threadIdx.x >> 5;
    int v = (i < n) ? oo.deg[t][i] : 0;
    int incl = v;
    #pragma unroll
    for (int o = 1; o < 32; o <<= 1) {
        int x = __shfl_up_sync(0xffffffffu, incl, o);
        if (lane >= o) incl += x;
    }
    __shared__ int ws[8];
    if (lane == 31) ws[wid] = incl;
    __syncthreads();
    if (wid == 0 && lane < 8) {
        int s = ws[lane];
        int ic = s;
        #pragma unroll
        for (int o = 1; o < 8; o <<= 1) {
            int x = __shfl_up_sync(0xffu, ic, o, 8);
            if (lane >= o) ic += x;
        }
        ws[lane] = ic - s;
    }
    __syncthreads();
    int base = oo.bsum[t][b] + ws[wid] + incl - v;
    if (i < n) { oo.off[t][i] = base; oo.cur[t][i] = base; }
    if (i == n - 1) oo.off[t][n] = base + v;
}

struct FillB { const int* dst[2]; const int* src[2]; int* cur[2]; int* csrc[2]; int E[2]; };

__global__ void fill_b(FillB fb)
{
    const int t = blockIdx.y;
    const int* __restrict__ dst = fb.dst[t];
    const int* __restrict__ src = fb.src[t];
    int* __restrict__ cur = fb.cur[t];
    int* __restrict__ csrc = fb.csrc[t];
    const int E = fb.E[t];
    for (int e = blockIdx.x * blockDim.x + threadIdx.x; e < E; e += gridDim.x * blockDim.x) {
        int p = atomicAdd(&cur[dst[e]], 1);
        csrc[p] = src[e];
    }
}

// ------------- fused edge pass: 8-lane-group-per-edge, half2 math, fp16 k ----------------
struct EdgeBatch {
    const unsigned char* qv[2];
    const __half* k[2];
    const int* off[2];
    const int* csrc[2];
    __nv_bfloat16* agg[2];
    float* psum;                 // [2]
    int n[2];
};

__device__ __forceinline__ void dec8h(unsigned u, __half2& a, __half2& b)
{
    unsigned r0, r1;
    asm("cvt.rn.f16x2.e4m3x2 %0, %1;" : "=r"(r0) : "h"((unsigned short)(u & 0xffffu)));
    asm("cvt.rn.f16x2.e4m3x2 %0, %1;" : "=r"(r1) : "h"((unsigned short)(u >> 16)));
    a = *(__half2*)&r0;
    b = *(__half2*)&r1;
}

__device__ __forceinline__ float lrexp(float p)
{
    float sc = p * 0.08838834764831845f;     // 1/sqrt(128)
    sc = sc > 0.f ? sc : 0.01f * sc;         // leaky_relu
    return __expf(sc);
}

__device__ __forceinline__ float dot16h(uint4 qw, const __half2* k2)
{
    __half2 a0, a1, b0, b1, c0, c1, d0, d1;
    dec8h(qw.x, a0, a1);
    dec8h(qw.y, b0, b1);
    dec8h(qw.z, c0, c1);
    dec8h(qw.w, d0, d1);
    __half2 s = __hmul2(a0, k2[0]);
    s = __hfma2(a1, k2[1], s);
    s = __hfma2(b0, k2[2], s);
    s = __hfma2(b1, k2[3], s);
    s = __hfma2(c0, k2[4], s);
    s = __hfma2(c1, k2[5], s);
    s = __hfma2(d0, k2[6], s);
    s = __hfma2(d1, k2[7], s);
    float2 f = __half22float2(s);
    return f.x + f.y;
}

__device__ __forceinline__ void acc16h(__half2 e2, uint4 vw, __half2* acc2)
{
    __half2 a0, a1, b0, b1, c0, c1, d0, d1;
    dec8h(vw.x, a0, a1);
    dec8h(vw.y, b0, b1);
    dec8h(vw.z, c0, c1);
    dec8h(vw.w, d0, d1);
    acc2[0] = __hfma2(e2, a0, acc2[0]);
    acc2[1] = __hfma2(e2, a1, acc2[1]);
    acc2[2] = __hfma2(e2, b0, acc2[2]);
    acc2[3] = __hfma2(e2, b1, acc2[3]);
    acc2[4] = __hfma2(e2, c0, acc2[4]);
    acc2[5] = __hfma2(e2, c1, acc2[5]);
    acc2[6] = __hfma2(e2, d0, acc2[6]);
    acc2[7] = __hfma2(e2, d1, acc2[7]);
}

__global__ __launch_bounds__(256) void fused_edge_batch(EdgeBatch eb)
{
    const int p    = blockIdx.y;
    const int lane = threadIdx.x & 31;
    const int grp  = lane >> 3;          // 0..3: which edge within a 4-edge slab
    const int gl   = lane & 7;           // 0..7: which 16-byte slice of the row
    const int warp = (blockIdx.x * 256 + threadIdx.x) >> 5;
    const int nw   = (gridDim.x * 256) >> 5;
    const unsigned char* __restrict__ qv = eb.qv[p] + gl * 16;
    const __half* __restrict__ kk = eb.k[p];
    const int* __restrict__ off  = eb.off[p];
    const int* __restrict__ csrc = eb.csrc[p];
    __nv_bfloat16* __restrict__ agg = eb.agg[p];
    const int n = eb.n[p];

    float S = 0.f;
    for (int node = warp; node < n; node += nw) {
        __half2 k2[8];
        {
            const __half* krow = kk + (size_t)node * D + gl * 16;
            uint4 kk0 = *(const uint4*)(krow);
            uint4 kk1 = *(const uint4*)(krow + 8);
            k2[0] = *(__half2*)&kk0.x; k2[1] = *(__half2*)&kk0.y;
            k2[2] = *(__half2*)&kk0.z; k2[3] = *(__half2*)&kk0.w;
            k2[4] = *(__half2*)&kk1.x; k2[5] = *(__half2*)&kk1.y;
            k2[6] = *(__half2*)&kk1.z; k2[7] = *(__half2*)&kk1.w;
        }
        __half2 acc2[8];
        #pragma unroll
        for (int i = 0; i < 8; ++i) acc2[i] = __floats2half2_rn(0.f, 0.f);

        const int beg = off[node], end = off[node + 1];
        int base = beg;
        for (; base + 8 <= end; base += 8) {
            int cA = csrc[base + grp];
            int cB = csrc[base + 4 + grp];
            const unsigned char* bpA = qv + (size_t)cA * ROWB;
            const unsigned char* bpB = qv + (size_t)cB * ROWB;
            uint4 qA = *(const uint4*)(bpA);
            uint4 qB = *(const uint4*)(bpB);
            uint4 vA = *(const uint4*)(bpA + 128);
            uint4 vB = *(const uint4*)(bpB + 128);
            float pA = dot16h(qA, k2);
            float pB = dot16h(qB, k2);
            #pragma unroll
            for (int o = 4; o; o >>= 1) {
                pA += __shfl_xor_sync(0xffffffffu, pA, o);
                pB += __shfl_xor_sync(0xffffffffu, pB, o);
            }
            float eA = lrexp(pA);
            float eB = lrexp(pB);
            acc16h(__float2half2_rn(eA), vA, acc2);
            acc16h(__float2half2_rn(eB), vB, acc2);
            if (gl == 0) S += eA + eB;
        }
        for (; base < end; base += 4) {
            int idx = base + grp;
            bool valid = idx < end;
            int c = valid ? csrc[idx] : 0;
            const unsigned char* bp = qv + (size_t)c * ROWB;
            uint4 q = *(const uint4*)(bp);
            uint4 v = *(const uint4*)(bp + 128);
            float pe = dot16h(q, k2);
            #pragma unroll
            for (int o = 4; o; o >>= 1) pe += __shfl_xor_sync(0xffffffffu, pe, o);
            float e = valid ? lrexp(pe) : 0.f;
            acc16h(__float2half2_rn(e), v, acc2);
            if (gl == 0) S += e;
        }

        #pragma unroll
        for (int i = 0; i < 8; ++i) {
            unsigned u = *(unsigned*)&acc2[i];
            unsigned u8  = __shfl_xor_sync(0xffffffffu, u, 8);
            __half2 t = __hadd2(acc2[i], *(__half2*)&u8);
            unsigned ut = *(unsigned*)&t;
            unsigned u16 = __shfl_xor_sync(0xffffffffu, ut, 16);
            acc2[i] = __hadd2(t, *(__half2*)&u16);
        }
        if (grp == 0) {
            unsigned w[8];
            #pragma unroll
            for (int j = 0; j < 8; ++j) {
                float2 f = __half22float2(acc2[j]);
                __nv_bfloat162 b2 = __floats2bfloat162_rn(f.x, f.y);
                w[j] = *(unsigned*)&b2;
            }
            __nv_bfloat16* arow = agg + (size_t)node * D + gl * 16;
            *(uint4*)(arow)     = make_uint4(w[0], w[1], w[2], w[3]);
            *(uint4*)(arow + 8) = make_uint4(w[4], w[5], w[6], w[7]);
        }
    }
    #pragma unroll
    for (int o = 16; o; o >>= 1) S += __shfl_xor_sync(0xffffffffu, S, o);
    if (lane == 0 && S != 0.f) atomicAdd(&eb.psum[p], S);
}

// ---- layer-0 epilogue: xb = bf16(x + agg/S) ----
struct Axpy0 {
    const float* xin[2];
    const __nv_bfloat16* agg[2];
    const float* gsum[2];
    __nv_bfloat16* outb[2];
    int n8[2];
};

__global__ void axpy0_batch(Axpy0 ab)
{
    const int t = blockIdx.y;
    int i = blockIdx.x * blockDim.x + threadIdx.x;
    if (i >= ab.n8[t]) return;
    float inv = 1.0f / *ab.gsum[t];
    const float4* xp = (const float4*)ab.xin[t] + i * 2;
    float4 x0 = xp[0];
    float4 x1 = xp[1];
    uint4 ag = ((const uint4*)ab.agg[t])[i];
    float2 a0 = __bfloat1622float2(*(__nv_bfloat162*)&ag.x);
    float2 a1 = __bfloat1622float2(*(__nv_bfloat162*)&ag.y);
    float2 a2 = __bfloat1622float2(*(__nv_bfloat162*)&ag.z);
    float2 a3 = __bfloat1622float2(*(__nv_bfloat162*)&ag.w);
    __nv_bfloat162 o0 = __floats2bfloat162_rn(fmaf(inv, a0.x, x0.x), fmaf(inv, a0.y, x0.y));
    __nv_bfloat162 o1 = __floats2bfloat162_rn(fmaf(inv, a1.x, x0.z), fmaf(inv, a1.y, x0.w));
    __nv_bfloat162 o2 = __floats2bfloat162_rn(fmaf(inv, a2.x, x1.x), fmaf(inv, a2.y, x1.y));
    __nv_bfloat162 o3 = __floats2bfloat162_rn(fmaf(inv, a3.x, x1.z), fmaf(inv, a3.y, x1.w));
    ((uint4*)ab.outb[t])[i] = make_uint4(*(unsigned*)&o0, *(unsigned*)&o1,
                                         *(unsigned*)&o2, *(unsigned*)&o3);
}

// ---- layer-1 epilogue: out = x + aggA/SA + aggB/SB ----
struct Axpy1 {
    const float* xin[2];
    const __nv_bfloat16* aggA[2];   // layer-0 agg
    const __nv_bfloat16* aggB[2];   // layer-1 agg
    const float* gsumA[2];
    const float* gsumB[2];
    float* out[2];
    int n8[2];
};

__global__ void axpy1_batch(Axpy1 ab)
{
    const int t = blockIdx.y;
    int i = blockIdx.x * blockDim.x + threadIdx.x;
    if (i >= ab.n8[t]) return;
    float invA = 1.0f / *ab.gsumA[t];
    float invB = 1.0f / *ab.gsumB[t];
    const float4* xp = (const float4*)ab.xin[t] + i * 2;
    float4 x0 = xp[0];
    float4 x1 = xp[1];
    uint4 gA = ((const uint4*)ab.aggA[t])[i];
    uint4 gB = ((const uint4*)ab.aggB[t])[i];
    float2 A0 = __bfloat1622float2(*(__nv_bfloat162*)&gA.x);
    float2 A1 = __bfloat1622float2(*(__nv_bfloat162*)&gA.y);
    float2 A2 = __bfloat1622float2(*(__nv_bfloat162*)&gA.z);
    float2 A3 = __bfloat1622float2(*(__nv_bfloat162*)&gA.w);
    float2 B0 = __bfloat1622float2(*(__nv_bfloat162*)&gB.x);
    float2 B1 = __bfloat1622float2(*(__nv_bfloat162*)&gB.y);
    float2 B2 = __bfloat1622float2(*(__nv_bfloat162*)&gB.z);
    float2 B3 = __bfloat1622float2(*(__nv_bfloat162*)&gB.w);
    float4 o0, o1;
    o0.x = fmaf(invB, B0.x, fmaf(invA, A0.x, x0.x));
    o0.y = fmaf(invB, B0.y, fmaf(invA, A0.y, x0.y));
    o0.z = fmaf(invB, B1.x, fmaf(invA, A1.x, x0.z));
    o0.w = fmaf(invB, B1.y, fmaf(invA, A1.y, x0.w));
    o1.x = fmaf(invB, B2.x, fmaf(invA, A2.x, x1.x));
    o1.y = fmaf(invB, B2.y, fmaf(invA, A2.y, x1.y));
    o1.z = fmaf(invB, B3.x, fmaf(invA, A3.x, x1.z));
    o1.w = fmaf(invB, B3.y, fmaf(invA, A3.y, x1.w));
    float4* op = (float4*)ab.out[t] + i * 2;
    op[0] = o0;
    op[1] = o1;
}

// ---------------- host-side orchestration ----------------
#define GEMM_SMEM (2 * 128 * GSTRIDE * (int)sizeof(__nv_bfloat16))

extern "C" void kernel_launch(void* const* d_in, const int* in_sizes, int n_in,
                              void* d_out, int out_size)
{
    const float* x_user = (const float*)d_in[0];
    const float* x_item = (const float*)d_in[1];
    const int*   ei_ui  = (const int*)d_in[2];
    const int*   ei_iu  = (const int*)d_in[3];
    const float* q_w_user = (const float*)d_in[4];
    const float* q_b_user = (const float*)d_in[5];
    const float* k_w_user = (const float*)d_in[6];
    const float* k_b_user = (const float*)d_in[7];
    const float* v_w_user = (const float*)d_in[8];
    const float* v_b_user = (const float*)d_in[9];
    const float* q_w_item = (const float*)d_in[10];
    const float* q_b_item = (const float*)d_in[11];
    const float* k_w_item = (const float*)d_in[12];
    const float* k_b_item = (const float*)d_in[13];
    const float* v_w_item = (const float*)d_in[14];
    const float* v_b_item = (const float*)d_in[15];
    const float* W_ui = (const float*)d_in[16];
    const float* W_iu = (const float*)d_in[17];

    const int NU = in_sizes[0] / D;
    const int NI = in_sizes[1] / D;
    const int E_ui = in_sizes[2] / 2;
    const int E_iu = in_sizes[3] / 2;

    cudaFuncSetAttribute(gemm_batch, cudaFuncAttributeMaxDynamicSharedMemorySize, GEMM_SMEM);

    // side stream + events for captured fork/join (created once; host-side only)
    static cudaStream_t s1 = nullptr;
    static cudaEvent_t evStart = nullptr, evCsr = nullptr;
    if (!s1) {
        cudaStreamCreateWithFlags(&s1, cudaStreamNonBlocking);
        cudaEventCreateWithFlags(&evStart, cudaEventDisableTiming);
        cudaEventCreateWithFlags(&evCsr, cudaEventDisableTiming);
    }

    float *cb, *psum;
    __nv_bfloat16 *agg, *xbu, *xbi, *Mtb, *Kb, *Vb;
    __half *kb0, *kb1;
    unsigned char *qv0, *qv1;
    int *deg0, *deg1, *cur0, *cur1, *bs0, *bs1, *off_ui, *off_iu, *src_ui_c, *src_iu_c;
    cudaGetSymbolAddress((void**)&agg, g_agg);       // [4][MAXN*D]
    cudaGetSymbolAddress((void**)&xbu, g_xbu);
    cudaGetSymbolAddress((void**)&xbi, g_xbi);
    cudaGetSymbolAddress((void**)&qv0, g_qv8);
    qv1 = qv0 + (size_t)MAXN * ROWB;
    cudaGetSymbolAddress((void**)&kb0, g_k);
    kb1 = kb0 + (size_t)MAXN * D;
    cudaGetSymbolAddress((void**)&Mtb, g_Mtb);
    cudaGetSymbolAddress((void**)&Kb, g_Kb);
    cudaGetSymbolAddress((void**)&Vb, g_Vb);
    cudaGetSymbolAddress((void**)&cb, g_cb);
    cudaGetSymbolAddress((void**)&psum, g_sum);
    cudaGetSymbolAddress((void**)&deg0, g_deg);
    deg1 = deg0 + MAXN;
    cudaGetSymbolAddress((void**)&cur0, g_cur);
    cur1 = cur0 + MAXN;
    cudaGetSymbolAddress((void**)&bs0, g_bsum);
    bs1 = bs0 + 260;
    cudaGetSymbolAddress((void**)&off_ui, g_off_ui);
    cudaGetSymbolAddress((void**)&off_iu, g_off_iu);
    cudaGetSymbolAddress((void**)&src_ui_c, g_src_ui);
    cudaGetSymbolAddress((void**)&src_iu_c, g_src_iu);

    __nv_bfloat16* aggP[4];
    for (int p = 0; p < 4; ++p) aggP[p] = agg + (size_t)p * MAXN * D;

    const int* src_ui = ei_ui;
    const int* dst_ui = ei_ui + E_ui;
    const int* src_iu = ei_iu;
    const int* dst_iu = ei_iu + E_iu;

    // ---- fork: side stream builds CSR while main stream does prep/conv/gemm0 ----
    cudaEventRecord(evStart, 0);
    cudaStreamWaitEvent(s1, evStart, 0);

    // === side stream: CSR chain ===
    cudaMemsetAsync(deg0, 0, 2 * (size_t)MAXN * sizeof(int), s1);
    {
        CountB cbt;
        cbt.dst[0] = dst_ui; cbt.deg[0] = deg0; cbt.E[0] = E_ui;
        cbt.dst[1] = dst_iu; cbt.deg[1] = deg1; cbt.E[1] = E_iu;
        count_b<<<dim3(512, 2), 256, 0, s1>>>(cbt);
    }
    const int nblk0 = (NI + 255) / 256;
    const int nblk1 = (NU + 255) / 256;
    const int nblkM = (nblk0 > nblk1) ? nblk0 : nblk1;
    {
        PartB pp;
        pp.deg[0] = deg0; pp.bsum[0] = bs0; pp.n[0] = NI;
        pp.deg[1] = deg1; pp.bsum[1] = bs1; pp.n[1] = NU;
        partial_b<<<dim3(nblkM, 2), 256, 0, s1>>>(pp);
        SSumB ss;
        ss.bsum[0] = bs0; ss.nblk[0] = nblk0;
        ss.bsum[1] = bs1; ss.nblk[1] = nblk1;
        scansums_b<<<1, 512, 0, s1>>>(ss);
        OffB oo;
        oo.deg[0] = deg0; oo.bsum[0] = bs0; oo.off[0] = off_ui; oo.cur[0] = cur0; oo.n[0] = NI;
        oo.deg[1] = deg1; oo.bsum[1] = bs1; oo.off[1] = off_iu; oo.cur[1] = cur1; oo.n[1] = NU;
        offsets_b<<<dim3(nblkM, 2), 256, 0, s1>>>(oo);
        FillB fbt;
        fbt.dst[0] = dst_ui; fbt.src[0] = src_ui; fbt.cur[0] = cur0; fbt.csrc[0] = src_ui_c; fbt.E[0] = E_ui;
        fbt.dst[1] = dst_iu; fbt.src[1] = src_iu; fbt.cur[1] = cur1; fbt.csrc[1] = src_iu_c; fbt.E[1] = E_iu;
        fill_b<<<dim3(512, 2), 256, 0, s1>>>(fbt);
    }
    cudaEventRecord(evCsr, s1);

    // === main stream: weight prep + conv ===
    {
        PrepBatch pb;
        for (int l = 0; l < 2; ++l) {
            const size_t wo = (size_t)l * D * D;
            const size_t bo = (size_t)l * D;
            pb.qw[2*l+0] = q_w_user + wo; pb.qb[2*l+0] = q_b_user + bo; pb.W[2*l+0] = W_ui + wo;
            pb.kw[2*l+0] = k_w_item + wo; pb.vw[2*l+0] = v_w_user + wo;
            pb.qw[2*l+1] = q_w_item + wo; pb.qb[2*l+1] = q_b_item + bo; pb.W[2*l+1] = W_iu + wo;
            pb.kw[2*l+1] = k_w_user + wo; pb.vw[2*l+1] = v_w_item + wo;
        }
        pb.Mtb = Mtb; pb.Kb = Kb; pb.Vb = Vb; pb.cb = cb; pb.psum = psum;
        prep_batch<<<dim3(193, 4), 256>>>(pb);
    }

    const int maxN = (NU > NI) ? NU : NI;
    const int n8grid = (maxN * D / 8 + 255) / 256;
    {
        ConvB cv;
        cv.x[0] = x_user; cv.y[0] = xbu; cv.n8[0] = NU * D / 8;
        cv.x[1] = x_item; cv.y[1] = xbi; cv.n8[1] = NI * D / 8;
        conv_b16<<<dim3(n8grid, 2), 256>>>(cv);
    }

    float* out_f = (float*)d_out;

    for (int l = 0; l < 2; ++l) {
        const size_t bo = (size_t)l * D;
        const int p0 = 2 * l, p1 = 2 * l + 1;

        GemmBatch gb;
        gb.X[0] = xbu; gb.W[0] = Mtb + p0 * D * D; gb.bias[0] = cb + p0 * D;    gb.C[0] = (char*)qv0;         gb.N[0] = NU; gb.mode[0] = 1;
        gb.X[1] = xbi; gb.W[1] = Kb + p0 * D * D;  gb.bias[1] = k_b_item + bo; gb.C[1] = (char*)kb0;         gb.N[1] = NI; gb.mode[1] = 2;
        gb.X[2] = xbu; gb.W[2] = Vb + p0 * D * D;  gb.bias[2] = v_b_user + bo; gb.C[2] = (char*)(qv0 + 128); gb.N[2] = NU; gb.mode[2] = 1;
        gb.X[3] = xbi; gb.W[3] = Mtb + p1 * D * D; gb.bias[3] = cb + p1 * D;    gb.C[3] = (char*)qv1;         gb.N[3] = NI; gb.mode[3] = 1;
        gb.X[4] = xbu; gb.W[4] = Kb + p1 * D * D;  gb.bias[4] = k_b_user + bo; gb.C[4] = (char*)kb1;         gb.N[4] = NU; gb.mode[4] = 2;
        gb.X[5] = xbi; gb.W[5] = Vb + p1 * D * D;  gb.bias[5] = v_b_item + bo; gb.C[5] = (char*)(qv1 + 128); gb.N[5] = NI; gb.mode[5] = 1;
        gemm_batch<<<dim3((maxN + 127) / 128, 6), 256, GEMM_SMEM>>>(gb);

        if (l == 0) cudaStreamWaitEvent(0, evCsr, 0);   // join: edge needs CSR

        EdgeBatch eb;
        eb.qv[0] = qv0; eb.k[0] = kb0;
        eb.off[0] = off_ui; eb.csrc[0] = src_ui_c; eb.agg[0] = aggP[p0]; eb.n[0] = NI;
        eb.qv[1] = qv1; eb.k[1] = kb1;
        eb.off[1] = off_iu; eb.csrc[1] = src_iu_c; eb.agg[1] = aggP[p1]; eb.n[1] = NU;
        eb.psum = psum + 2 * l;
        fused_edge_batch<<<dim3(1024, 2), 256>>>(eb);

        if (l == 0) {
            Axpy0 a0;
            a0.xin[0] = x_user; a0.agg[0] = aggP[1]; a0.gsum[0] = psum + 1; a0.outb[0] = xbu; a0.n8[0] = NU * D / 8;
            a0.xin[1] = x_item; a0.agg[1] = aggP[0]; a0.gsum[1] = psum + 0; a0.outb[1] = xbi; a0.n8[1] = NI * D / 8;
            axpy0_batch<<<dim3(n8grid, 2), 256>>>(a0);
        } else {
            Axpy1 a1;
            a1.xin[0] = x_user; a1.aggA[0] = aggP[1]; a1.aggB[0] = aggP[3];
            a1.gsumA[0] = psum + 1; a1.gsumB[0] = psum + 3;
            a1.out[0] = out_f; a1.n8[0] = NU * D / 8;
            a1.xin[1] = x_item; a1.aggA[1] = aggP[0]; a1.aggB[1] = aggP[2];
            a1.gsumA[1] = psum + 0; a1.gsumB[1] = psum + 2;
            a1.out[1] = out_f + (size_t)NU * D; a1.n8[1] = NI * D / 8;
            axpy1_batch<<<dim3(n8grid, 2), 256>>>(a1);
        }
    }
}